// round 16
// baseline (speedup 1.0000x reference)
#include <cuda_runtime.h>
#include <math.h>

#define V 32000
#define EDIM 256
#define HDIM 128
#define BB 64
#define SS 1024
#define TT 4

typedef unsigned long long ull;

// ---------------- scratch (static device globals) ---------------------------
__device__ float g_table[V * 1024];     // [v][dir*512 + g] : PURE x@W_ih.T
__device__ float g_h[SS * BB * 256];    // [s][b][dir*128 + j]
__device__ float g_feats[BB * SS * TT]; // [b][s][t]
__device__ int   g_dummy;

// ---------------- packed f32x2 helpers --------------------------------------
__device__ __forceinline__ void fma2(ull &acc, ull a, ull b) {
    asm("fma.rn.f32x2 %0, %1, %2, %0;" : "+l"(acc) : "l"(a), "l"(b));
}
__device__ __forceinline__ ull pack2(float lo, float hi) {
    ull r; asm("mov.b64 %0, {%1, %2};" : "=l"(r) : "f"(lo), "f"(hi)); return r;
}
__device__ __forceinline__ void unpack2(ull v, float &lo, float &hi) {
    asm("mov.b64 {%0, %1}, %2;" : "=f"(lo), "=f"(hi) : "l"(v));
}

// ---------------- cp.async helpers ------------------------------------------
__device__ __forceinline__ void cpasync4(unsigned int dst, const float* src) {
    asm volatile("cp.async.ca.shared.global [%0], [%1], 4;"
                 :: "r"(dst), "l"(src));
}
__device__ __forceinline__ void cpasync_commit() {
    asm volatile("cp.async.commit_group;");
}
__device__ __forceinline__ void cpasync_wait0() {
    asm volatile("cp.async.wait_group 0;");
}

// ---------------- XLA-GPU exact nonlinearities ------------------------------
__device__ __forceinline__ float tanh_xla(float x) {
    float ax = fabsf(x);
    float xc = fminf(fmaxf(x, -7.90531110763549805f), 7.90531110763549805f);
    float x2 = __fmul_rn(xc, xc);
    float p = __fmaf_rn(x2, -2.76076847742355e-16f, 2.00018790482477e-13f);
    p = __fmaf_rn(x2, p, -8.60467152213735e-11f);
    p = __fmaf_rn(x2, p,  5.12229709037114e-08f);
    p = __fmaf_rn(x2, p,  1.48572235717979e-05f);
    p = __fmaf_rn(x2, p,  6.37261928875436e-04f);
    p = __fmaf_rn(x2, p,  4.89352455891786e-03f);
    float num = __fmul_rn(xc, p);
    float q = __fmaf_rn(x2, 1.19825839466702e-06f, 1.18534705686654e-04f);
    q = __fmaf_rn(x2, q, 2.26843463243900e-03f);
    q = __fmaf_rn(x2, q, 4.89352518554385e-03f);
    float r = __fdiv_rn(num, q);
    float ft = (ax < 0.0004f) ? x : r;
    return (ax < 20.0f) ? ft : copysignf(1.0f, x);
}
__device__ __forceinline__ float sigmoid_xla(float x) {
    float t = tanh_xla(__fmul_rn(0.5f, x));
    return __fadd_rn(__fmul_rn(0.5f, t), 0.5f);
}

// ---------------- dummy launch-shifter (for ncu capture alignment) ----------
__global__ void kdummy() { if (threadIdx.x == 0) g_dummy = 1; }

// =====================================================================
// K1: g_table[v][ng] = embed[v] . W_ih[dir][g]  (pure projection)
// Round-15 math (natural As, register {a,a} packs — bit-identical table)
// + cp.async double-buffered tile pipeline: tile t+1's global->smem copies
// run asynchronously under tile t's compute; no register staging.
// =====================================================================
#define K1_TILE_BYTES (16 * 132 * 4)        // float[16][132]
#define K1_SMEM       (4 * K1_TILE_BYTES)   // As x2 bufs + Bs x2 bufs

__global__ void __launch_bounds__(256, 2) k1_table(
    const float* __restrict__ embed,
    const float* __restrict__ w_ih_f, const float* __restrict__ w_ih_r)
{
    extern __shared__ __align__(16) char k1sm[];
    float* AsBuf[2] = { (float*)k1sm, (float*)(k1sm + K1_TILE_BYTES) };
    float* BsBuf[2] = { (float*)(k1sm + 2 * K1_TILE_BYTES),
                        (float*)(k1sm + 3 * K1_TILE_BYTES) };
    const unsigned int smem_base =
        (unsigned int)__cvta_generic_to_shared(k1sm);

    const int tid  = threadIdx.x;
    const int row0 = blockIdx.y * 128;
    const int n0   = blockIdx.x * 128;
    const int tx = tid & 15, ty = tid >> 4;

    ull acc[8][4];
    #pragma unroll
    for (int m = 0; m < 8; ++m)
        #pragma unroll
        for (int n2 = 0; n2 < 4; ++n2) acc[m][n2] = 0ull;

    // async copy of one BK=16 tile into buffer `buf`
    auto issue_tile = [&](int t, int buf) {
        const int k0 = t * 16;
        const unsigned int aBase = smem_base + buf * K1_TILE_BYTES;
        const unsigned int bBase = smem_base + (2 + buf) * K1_TILE_BYTES;
        #pragma unroll
        for (int i = 0; i < 8; ++i) {
            int lin = tid + 256 * i;
            int m = lin >> 4, k = lin & 15;
            cpasync4(aBase + (unsigned)(k * 132 + m) * 4,
                     embed + (size_t)(row0 + m) * EDIM + k0 + k);
            int ng = n0 + m;
            const float* src = (ng >= 512) ? w_ih_r : w_ih_f;
            cpasync4(bBase + (unsigned)(k * 132 + m) * 4,
                     src + (size_t)(ng & 511) * EDIM + k0 + k);
        }
        cpasync_commit();
    };

    issue_tile(0, 0);
    cpasync_wait0();
    __syncthreads();

    for (int t = 0; t < 16; ++t) {
        const int buf = t & 1;
        if (t < 15) issue_tile(t + 1, buf ^ 1);   // overlaps compute below

        const float* As = AsBuf[buf];
        const float* Bs = BsBuf[buf];
        #pragma unroll
        for (int kk = 0; kk < 16; ++kk) {
            float4 a0 = *(const float4*)&As[kk * 132 + ty * 8];
            float4 a1 = *(const float4*)&As[kk * 132 + ty * 8 + 4];
            ulonglong2 b01 = *(const ulonglong2*)&Bs[kk * 132 + tx * 8];
            ulonglong2 b23 = *(const ulonglong2*)&Bs[kk * 132 + tx * 8 + 4];
            float am[8] = { a0.x, a0.y, a0.z, a0.w, a1.x, a1.y, a1.z, a1.w };
            ull bp[4] = { b01.x, b01.y, b23.x, b23.y };
            #pragma unroll
            for (int m = 0; m < 8; ++m) {
                ull ad = pack2(am[m], am[m]);
                #pragma unroll
                for (int n2 = 0; n2 < 4; ++n2)
                    fma2(acc[m][n2], ad, bp[n2]);
            }
        }

        if (t < 15) {
            cpasync_wait0();
            __syncthreads();
        }
    }

    #pragma unroll
    for (int m = 0; m < 8; ++m) {
        int row = row0 + ty * 8 + m;
        float o[8];
        #pragma unroll
        for (int n2 = 0; n2 < 4; ++n2)
            unpack2(acc[m][n2], o[2 * n2], o[2 * n2 + 1]);
        float* dst = g_table + (size_t)row * 1024 + n0 + tx * 8;
        *(float4*)dst       = make_float4(o[0], o[1], o[2], o[3]);
        *(float4*)(dst + 4) = make_float4(o[4], o[5], o[6], o[7]);
    }
}

// =====================================================================
// K2: LSTM recurrence, f32x2. 128 CTAs = (b, dir), 256 threads.
// Round-15 version, 2-STEP UNROLLED: ping-pong h buffers hardwired
// (no (s&1) selects), loop overhead halved. All arithmetic identical
// -> bit-identical h -> rel_err 0.
// =====================================================================
#define K2_WSQ  8
#define K2_WS   (K2_WSQ * 256 * 16)            // ulonglong2[8][256] = 32 KB
#define K2_SMEM (K2_WS + 2048 + 4096)          // + hd[2][128] float2 + toks

__global__ void __launch_bounds__(256, 1) k2_lstm(
    const int* __restrict__ sentences,
    const float* __restrict__ w_hh_f, const float* __restrict__ w_hh_r,
    const float* __restrict__ b_ih_f, const float* __restrict__ b_hh_f,
    const float* __restrict__ b_ih_r, const float* __restrict__ b_hh_r)
{
    extern __shared__ __align__(16) char sm[];
    ulonglong2* wsP2 = (ulonglong2*)sm;                 // [8][256] : k=112..127
    float2* hd0  = (float2*)(sm + K2_WS);               // [128] {h,h}
    float2* hd1  = (float2*)(sm + K2_WS + 1024);        // [128] {h,h}
    int*    toks = (int*)  (sm + K2_WS + 2048);         // [1024]

    const int t   = threadIdx.x;
    const int u   = t >> 1;
    const int par = t & 1;           // 0: rows (i_u, g_u)  1: rows (f_u, o_u)
    const int rA  = par * 128 + u;
    const int dir = blockIdx.x & 1;
    const int b   = blockIdx.x >> 1;
    const float* Whh = dir ? w_hh_r : w_hh_f;
    const float* bi  = dir ? b_ih_r : b_ih_f;
    const float* bh  = dir ? b_hh_r : b_hh_f;

    const float bA = __fadd_rn(bi[rA],       bh[rA]);
    const float bB = __fadd_rn(bi[rA + 256], bh[rA + 256]);

    #pragma unroll
    for (int it = 0; it < 4; ++it) {
        int tk = sentences[b * SS + t + 256 * it];
        if (tk < 0) tk = 0;
        if (tk >= V) tk = V - 1;
        toks[t + 256 * it] = tk;
    }

    ull wregP[112];                // k = 0..111, {w_rA[k], w_rA+256[k]}
    {
        const float* r0 = Whh + (size_t)rA * HDIM;
        const float* r1 = Whh + (size_t)(rA + 256) * HDIM;
        #pragma unroll
        for (int k = 0; k < 112; ++k) wregP[k] = pack2(r0[k], r1[k]);
        #pragma unroll
        for (int qq = 0; qq < K2_WSQ; ++qq) {
            int k = 112 + 2 * qq;
            ulonglong2 w2;
            w2.x = pack2(r0[k],     r1[k]);
            w2.y = pack2(r0[k + 1], r1[k + 1]);
            wsP2[qq * 256 + t] = w2;
        }
    }

    float cst = 0.0f;
    if (par == 0) hd0[u] = make_float2(0.0f, 0.0f);
    __syncthreads();

    const float* tb = g_table + dir * 512 + rA;
    int pos = dir ? (SS - 1) : 0;
    const int stp = dir ? -1 : 1;

    const float* zrow = tb + (size_t)toks[pos] * 1024;
    float zl = zrow[0];
    float zh = zrow[256];

    // one LSTM step: read h from hpR, write new h into hdW
    auto step = [&](const ulonglong2* hpR, float2* hdW) {
        float nzl = 0.0f, nzh = 0.0f;
        int npos = pos + stp;
        if (npos >= 0 && npos < SS) {
            const float* np = tb + (size_t)toks[npos] * 1024;
            nzl = np[0]; nzh = np[256];
        }

        ull acc0 = 0ull, acc1 = 0ull, acc2 = 0ull, acc3 = 0ull;
        #pragma unroll
        for (int q = 0; q < 16; ++q) {
            ulonglong2 h2 = hpR[q];
            fma2(acc0, h2.x, wregP[2 * q]);
            fma2(acc0, h2.y, wregP[2 * q + 1]);
        }
        #pragma unroll
        for (int q = 16; q < 32; ++q) {
            ulonglong2 h2 = hpR[q];
            fma2(acc1, h2.x, wregP[2 * q]);
            fma2(acc1, h2.y, wregP[2 * q + 1]);
        }
        #pragma unroll
        for (int q = 32; q < 48; ++q) {
            ulonglong2 h2 = hpR[q];
            fma2(acc2, h2.x, wregP[2 * q]);
            fma2(acc2, h2.y, wregP[2 * q + 1]);
        }
        #pragma unroll
        for (int q = 48; q < 56; ++q) {
            ulonglong2 h2 = hpR[q];
            fma2(acc3, h2.x, wregP[2 * q]);
            fma2(acc3, h2.y, wregP[2 * q + 1]);
        }
        #pragma unroll
        for (int qq = 0; qq < K2_WSQ; ++qq) {
            ulonglong2 h2 = hpR[56 + qq];
            ulonglong2 w2 = wsP2[qq * 256 + t];
            fma2(acc3, h2.x, w2.x);
            fma2(acc3, h2.y, w2.y);
        }

        float a0l, a0h, a1l, a1h, a2l, a2h, a3l, a3h;
        unpack2(acc0, a0l, a0h);
        unpack2(acc1, a1l, a1h);
        unpack2(acc2, a2l, a2h);
        unpack2(acc3, a3l, a3h);
        float hwA = __fadd_rn(__fadd_rn(a0l, a1l), __fadd_rn(a2l, a3l));
        float hwB = __fadd_rn(__fadd_rn(a0h, a1h), __fadd_rn(a2h, a3h));

        float zA = __fadd_rn(__fadd_rn(zl, hwA), bA);   // par0: zi, par1: zf
        float zB = __fadd_rn(__fadd_rn(zh, hwB), bB);   // par0: zg, par1: zo

        float vA = sigmoid_xla(zA);
        float targ = par ? __fmul_rn(0.5f, zB) : zB;
        float tv   = tanh_xla(targ);
        float vB   = par ? __fadd_rn(__fmul_rn(0.5f, tv), 0.5f) : tv;

        ull opk = __shfl_xor_sync(0xffffffffu, pack2(vA, vB), 1);

        if (par == 0) {
            float iv = vA, gv = vB;
            float fv, ov; unpack2(opk, fv, ov);
            cst = __fadd_rn(__fmul_rn(fv, cst), __fmul_rn(iv, gv));
            float hv = __fmul_rn(ov, tanh_xla(cst));
            hdW[u] = make_float2(hv, hv);
            g_h[(size_t)(pos * BB + b) * 256 + dir * 128 + u] = hv;
        }
        __syncthreads();

        zl = nzl; zh = nzh;
        pos += stp;
    };

    #pragma unroll 1
    for (int s = 0; s < SS; s += 2) {
        step((const ulonglong2*)hd0, hd1);
        step((const ulonglong2*)hd1, hd0);
    }
}

// =====================================================================
// K3: emissions. One warp per (s,b).
// =====================================================================
__global__ void __launch_bounds__(256) k3_emis(
    const float* __restrict__ w_out, const float* __restrict__ b_out)
{
    __shared__ float wsm[4 * 256];
    int tid = threadIdx.x;
    #pragma unroll
    for (int it = 0; it < 4; ++it) wsm[tid + 256 * it] = w_out[tid + 256 * it];
    __syncthreads();

    int w = tid >> 5, lane = tid & 31;
    int gid = blockIdx.x * 8 + w;
    int b = gid & 63, s = gid >> 6;
    const float* hrow = g_h + (size_t)(s * BB + b) * 256;

    float a0 = 0.f, a1 = 0.f, a2 = 0.f, a3 = 0.f;
    #pragma unroll
    for (int it = 0; it < 8; ++it) {
        int jj = it * 32 + lane;
        float hv = hrow[jj];
        a0 = __fmaf_rn(hv, wsm[jj],       a0);
        a1 = __fmaf_rn(hv, wsm[256 + jj], a1);
        a2 = __fmaf_rn(hv, wsm[512 + jj], a2);
        a3 = __fmaf_rn(hv, wsm[768 + jj], a3);
    }
    #pragma unroll
    for (int off = 16; off; off >>= 1) {
        a0 = __fadd_rn(a0, __shfl_xor_sync(0xffffffffu, a0, off));
        a1 = __fadd_rn(a1, __shfl_xor_sync(0xffffffffu, a1, off));
        a2 = __fadd_rn(a2, __shfl_xor_sync(0xffffffffu, a2, off));
        a3 = __fadd_rn(a3, __shfl_xor_sync(0xffffffffu, a3, off));
    }
    if (lane == 0) {
        float* dst = g_feats + (size_t)(b * SS + s) * 4;
        dst[0] = __fadd_rn(a0, b_out[0]);
        dst[1] = __fadd_rn(a1, b_out[1]);
        dst[2] = __fadd_rn(a2, b_out[2]);
        dst[3] = __fadd_rn(a3, b_out[3]);
    }
}

// =====================================================================
// K4: Viterbi (float output) — unchanged; clock canary.
// =====================================================================
__global__ void __launch_bounds__(128) k4_viterbi(
    const float* __restrict__ start_t, const float* __restrict__ end_t,
    const float* __restrict__ trans, float* __restrict__ out)
{
    __shared__ float fs[SS * 4];
    __shared__ unsigned char bp[SS * 4];
    __shared__ int path[SS];
    int tid = threadIdx.x;
    int b = blockIdx.x;

    const float* src = g_feats + (size_t)b * SS * 4;
    for (int i = tid; i < SS * 4; i += 128) fs[i] = src[i];
    __syncthreads();

    if (tid < 4) {
        const int t = tid;
        float tr0 = trans[0 * 4 + t], tr1 = trans[1 * 4 + t];
        float tr2 = trans[2 * 4 + t], tr3 = trans[3 * 4 + t];
        float score = __fadd_rn(start_t[t], fs[t]);
        for (int s = 1; s < SS; ++s) {
            float s0 = __shfl_sync(0xFu, score, 0);
            float s1 = __shfl_sync(0xFu, score, 1);
            float s2 = __shfl_sync(0xFu, score, 2);
            float s3 = __shfl_sync(0xFu, score, 3);
            float e  = fs[s * 4 + t];
            float v0 = __fadd_rn(__fadd_rn(s0, tr0), e);
            float v1 = __fadd_rn(__fadd_rn(s1, tr1), e);
            float v2 = __fadd_rn(__fadd_rn(s2, tr2), e);
            float v3 = __fadd_rn(__fadd_rn(s3, tr3), e);
            float best = v0; int bpi = 0;
            if (v1 > best) { best = v1; bpi = 1; }
            if (v2 > best) { best = v2; bpi = 2; }
            if (v3 > best) { best = v3; bpi = 3; }
            score = best;
            bp[s * 4 + t] = (unsigned char)bpi;
        }
        score = __fadd_rn(score, end_t[t]);
        float f0 = __shfl_sync(0xFu, score, 0);
        float f1 = __shfl_sync(0xFu, score, 1);
        float f2 = __shfl_sync(0xFu, score, 2);
        float f3 = __shfl_sync(0xFu, score, 3);
        __syncwarp(0xFu);
        if (t == 0) {
            float best = f0; int last = 0;
            if (f1 > best) { best = f1; last = 1; }
            if (f2 > best) { best = f2; last = 2; }
            if (f3 > best) { best = f3; last = 3; }
            int tag = last;
            path[SS - 1] = tag;
            for (int s = SS - 1; s >= 1; --s) {
                tag = bp[s * 4 + tag];
                path[s - 1] = tag;
            }
        }
    }
    __syncthreads();
    for (int i = tid; i < SS; i += 128)
        out[b * SS + i] = (float)path[i];
}

// =====================================================================
extern "C" void kernel_launch(void* const* d_in, const int* in_sizes, int n_in,
                              void* d_out, int out_size)
{
    const int*   sentences = (const int*)d_in[0];
    const float* embed   = (const float*)d_in[1];
    const float* w_ih_f  = (const float*)d_in[2];
    const float* w_hh_f  = (const float*)d_in[3];
    const float* b_ih_f  = (const float*)d_in[4];
    const float* b_hh_f  = (const float*)d_in[5];
    const float* w_ih_r  = (const float*)d_in[6];
    const float* w_hh_r  = (const float*)d_in[7];
    const float* b_ih_r  = (const float*)d_in[8];
    const float* b_hh_r  = (const float*)d_in[9];
    const float* w_out   = (const float*)d_in[10];
    const float* b_out   = (const float*)d_in[11];
    const float* start_t = (const float*)d_in[12];
    const float* end_t   = (const float*)d_in[13];
    const float* trans   = (const float*)d_in[14];

    // launch-shifters keep ncu's capture window on k2_lstm
    kdummy<<<1, 32>>>();
    kdummy<<<1, 32>>>();

    cudaFuncSetAttribute(k1_table, cudaFuncAttributeMaxDynamicSharedMemorySize, K1_SMEM);
    dim3 g1(8, 250);
    k1_table<<<g1, 256, K1_SMEM>>>(embed, w_ih_f, w_ih_r);

    cudaFuncSetAttribute(k2_lstm, cudaFuncAttributeMaxDynamicSharedMemorySize, K2_SMEM);
    k2_lstm<<<128, 256, K2_SMEM>>>(sentences, w_hh_f, w_hh_r,
                                   b_ih_f, b_hh_f, b_ih_r, b_hh_r);

    k3_emis<<<8192, 256>>>(w_out, b_out);
    k4_viterbi<<<64, 128>>>(start_t, end_t, trans, (float*)d_out);
}

// round 17
// speedup vs baseline: 1.2049x; 1.2049x over previous
#include <cuda_runtime.h>
#include <math.h>

#define V 32000
#define EDIM 256
#define HDIM 128
#define BB 64
#define SS 1024
#define TT 4

typedef unsigned long long ull;

// ---------------- scratch (static device globals) ---------------------------
__device__ float g_table[V * 1024];     // [v][dir*512 + g] : PURE x@W_ih.T
__device__ float g_h[SS * BB * 256];    // [s][b][dir*128 + j]
__device__ float g_feats[BB * SS * TT]; // [b][s][t]
__device__ int   g_dummy;

// ---------------- packed f32x2 helpers --------------------------------------
__device__ __forceinline__ void fma2(ull &acc, ull a, ull b) {
    asm("fma.rn.f32x2 %0, %1, %2, %0;" : "+l"(acc) : "l"(a), "l"(b));
}
__device__ __forceinline__ ull pack2(float lo, float hi) {
    ull r; asm("mov.b64 %0, {%1, %2};" : "=l"(r) : "f"(lo), "f"(hi)); return r;
}
__device__ __forceinline__ void unpack2(ull v, float &lo, float &hi) {
    asm("mov.b64 {%0, %1}, %2;" : "=f"(lo), "=f"(hi) : "l"(v));
}

// ---------------- XLA-GPU exact nonlinearities ------------------------------
__device__ __forceinline__ float tanh_xla(float x) {
    float ax = fabsf(x);
    float xc = fminf(fmaxf(x, -7.90531110763549805f), 7.90531110763549805f);
    float x2 = __fmul_rn(xc, xc);
    float p = __fmaf_rn(x2, -2.76076847742355e-16f, 2.00018790482477e-13f);
    p = __fmaf_rn(x2, p, -8.60467152213735e-11f);
    p = __fmaf_rn(x2, p,  5.12229709037114e-08f);
    p = __fmaf_rn(x2, p,  1.48572235717979e-05f);
    p = __fmaf_rn(x2, p,  6.37261928875436e-04f);
    p = __fmaf_rn(x2, p,  4.89352455891786e-03f);
    float num = __fmul_rn(xc, p);
    float q = __fmaf_rn(x2, 1.19825839466702e-06f, 1.18534705686654e-04f);
    q = __fmaf_rn(x2, q, 2.26843463243900e-03f);
    q = __fmaf_rn(x2, q, 4.89352518554385e-03f);
    float r = __fdiv_rn(num, q);
    float ft = (ax < 0.0004f) ? x : r;
    return (ax < 20.0f) ? ft : copysignf(1.0f, x);
}
__device__ __forceinline__ float sigmoid_xla(float x) {
    float t = tanh_xla(__fmul_rn(0.5f, x));
    return __fadd_rn(__fmul_rn(0.5f, t), 0.5f);
}

// ---------------- dummy launch-shifter (for ncu capture alignment) ----------
__global__ void kdummy() { if (threadIdx.x == 0) g_dummy = 1; }

// =====================================================================
// K1: g_table[v][ng] = embed[v] . W_ih[dir][g]  (round-15 version: natural
// As, register {a,a} packs, LDG->reg->STS double buffer; bit-identical table)
// =====================================================================
#define K1_TILE_BYTES (16 * 132 * 4)        // float[16][132]
#define K1_SMEM       (4 * K1_TILE_BYTES)   // As x2 bufs + Bs x2 bufs

__global__ void __launch_bounds__(256, 2) k1_table(
    const float* __restrict__ embed,
    const float* __restrict__ w_ih_f, const float* __restrict__ w_ih_r)
{
    extern __shared__ __align__(16) char k1sm[];
    float* AsBuf[2] = { (float*)k1sm, (float*)(k1sm + K1_TILE_BYTES) };
    float* BsBuf[2] = { (float*)(k1sm + 2 * K1_TILE_BYTES),
                        (float*)(k1sm + 3 * K1_TILE_BYTES) };

    const int tid  = threadIdx.x;
    const int row0 = blockIdx.y * 128;
    const int n0   = blockIdx.x * 128;
    const int tx = tid & 15, ty = tid >> 4;

    ull acc[8][4];
    #pragma unroll
    for (int m = 0; m < 8; ++m)
        #pragma unroll
        for (int n2 = 0; n2 < 4; ++n2) acc[m][n2] = 0ull;

    float ra[8], rb[8];

    auto ldg_tile = [&](int t) {
        const int k0 = t * 16;
        #pragma unroll
        for (int i = 0; i < 8; ++i) {
            int lin = tid + 256 * i;
            int m = lin >> 4, k = lin & 15;
            ra[i] = embed[(size_t)(row0 + m) * EDIM + k0 + k];
            int ng = n0 + m;
            const float* src = (ng >= 512) ? w_ih_r : w_ih_f;
            rb[i] = src[(size_t)(ng & 511) * EDIM + k0 + k];
        }
    };
    auto sts_tile = [&](int buf) {
        #pragma unroll
        for (int i = 0; i < 8; ++i) {
            int lin = tid + 256 * i;
            int m = lin >> 4, k = lin & 15;
            AsBuf[buf][k * 132 + m] = ra[i];
            BsBuf[buf][k * 132 + m] = rb[i];
        }
    };

    ldg_tile(0);
    sts_tile(0);
    __syncthreads();

    for (int t = 0; t < 16; ++t) {
        const int buf = t & 1;
        if (t < 15) ldg_tile(t + 1);

        const float* As = AsBuf[buf];
        const float* Bs = BsBuf[buf];
        #pragma unroll
        for (int kk = 0; kk < 16; ++kk) {
            float4 a0 = *(const float4*)&As[kk * 132 + ty * 8];
            float4 a1 = *(const float4*)&As[kk * 132 + ty * 8 + 4];
            ulonglong2 b01 = *(const ulonglong2*)&Bs[kk * 132 + tx * 8];
            ulonglong2 b23 = *(const ulonglong2*)&Bs[kk * 132 + tx * 8 + 4];
            float am[8] = { a0.x, a0.y, a0.z, a0.w, a1.x, a1.y, a1.z, a1.w };
            ull bp[4] = { b01.x, b01.y, b23.x, b23.y };
            #pragma unroll
            for (int m = 0; m < 8; ++m) {
                ull ad = pack2(am[m], am[m]);
                #pragma unroll
                for (int n2 = 0; n2 < 4; ++n2)
                    fma2(acc[m][n2], ad, bp[n2]);
            }
        }

        if (t < 15) {
            sts_tile(buf ^ 1);
            __syncthreads();
        }
    }

    #pragma unroll
    for (int m = 0; m < 8; ++m) {
        int row = row0 + ty * 8 + m;
        float o[8];
        #pragma unroll
        for (int n2 = 0; n2 < 4; ++n2)
            unpack2(acc[m][n2], o[2 * n2], o[2 * n2 + 1]);
        float* dst = g_table + (size_t)row * 1024 + n0 + tx * 8;
        *(float4*)dst       = make_float4(o[0], o[1], o[2], o[3]);
        *(float4*)(dst + 4) = make_float4(o[4], o[5], o[6], o[7]);
    }
}

// =====================================================================
// K2: LSTM recurrence, f32x2 with K-HALF PACKING. 128 CTAs = (b, dir),
// 256 threads. Thread t: u = t>>1, par = t&1, rows rA = par*128+u and
// rB = rA+256.
// Operand pairs packed over (k, k+64):
//   h stored ONCE as float2 {h[k], h[k+64]} (512B) -> 32 broadcast
//   LDS.128/thread/step (halved); each h load feeds 4 fma2.
//   weights {W[r][k], W[r][k+64]}: k=0..55 in regs (112 ull), k=56..63 in
//   smem (8 LDS.128/thread, same as r15).
// Association preserved exactly:
//   accX0.lo = seq k0..31,  accX1.lo = seq k32..63,
//   accX0.hi = seq k64..95, accX1.hi = seq k96..127,
//   hw = (lo0+lo1)+(hi0+hi1)  ==  old (a0+a1)+(a2+a3)  -> bit-identical h.
// Parallel nonlinearity tail (r15). Single barrier per step.
// =====================================================================
#define K2_WS   (4 * 2 * 256 * 16)             // ulonglong2[4][2][256] = 32 KB
#define K2_SMEM (K2_WS + 2048 + 4096)          // + hd[2][64] float2 + toks

__global__ void __launch_bounds__(256, 1) k2_lstm(
    const int* __restrict__ sentences,
    const float* __restrict__ w_hh_f, const float* __restrict__ w_hh_r,
    const float* __restrict__ b_ih_f, const float* __restrict__ b_hh_f,
    const float* __restrict__ b_ih_r, const float* __restrict__ b_hh_r)
{
    extern __shared__ __align__(16) char sm[];
    ulonglong2* wsP2 = (ulonglong2*)sm;              // [4][2][256] : k=56..63
    float2* hd0  = (float2*)(sm + K2_WS);            // [64] {h[k], h[k+64]}
    float2* hd1  = (float2*)(sm + K2_WS + 1024);     // [64]
    int*    toks = (int*)  (sm + K2_WS + 2048);      // [1024]

    const int t   = threadIdx.x;
    const int u   = t >> 1;          // hidden unit 0..127
    const int par = t & 1;           // 0: rows (i_u, g_u)  1: rows (f_u, o_u)
    const int rA  = par * 128 + u;
    const int dir = blockIdx.x & 1;
    const int b   = blockIdx.x >> 1;
    const float* Whh = dir ? w_hh_r : w_hh_f;
    const float* bi  = dir ? b_ih_r : b_ih_f;
    const float* bh  = dir ? b_hh_r : b_hh_f;

    const float bA = __fadd_rn(bi[rA],       bh[rA]);
    const float bB = __fadd_rn(bi[rA + 256], bh[rA + 256]);

    #pragma unroll
    for (int it = 0; it < 4; ++it) {
        int tk = sentences[b * SS + t + 256 * it];
        if (tk < 0) tk = 0;
        if (tk >= V) tk = V - 1;
        toks[t + 256 * it] = tk;
    }

    // weight pairs {W[r][k], W[r][k+64]}: k = 0..55 in regs for both rows
    ull wregA[56], wregB[56];
    {
        const float* r0 = Whh + (size_t)rA * HDIM;
        const float* r1 = Whh + (size_t)(rA + 256) * HDIM;
        #pragma unroll
        for (int k = 0; k < 56; ++k) {
            wregA[k] = pack2(r0[k], r0[k + 64]);
            wregB[k] = pack2(r1[k], r1[k + 64]);
        }
        // k = 56..63 in smem: wsP2[(q-28)*2 + row][t]
        #pragma unroll
        for (int q = 28; q < 32; ++q) {
            int k = 2 * q;          // 56, 58, 60, 62
            ulonglong2 wa, wb;
            wa.x = pack2(r0[k],     r0[k + 64]);
            wa.y = pack2(r0[k + 1], r0[k + 65]);
            wb.x = pack2(r1[k],     r1[k + 64]);
            wb.y = pack2(r1[k + 1], r1[k + 65]);
            wsP2[((q - 28) * 2 + 0) * 256 + t] = wa;
            wsP2[((q - 28) * 2 + 1) * 256 + t] = wb;
        }
    }

    float cst = 0.0f;
    // zero h buffer 0: even threads cover all 128 slots via the bijection
    if (par == 0) ((float*)hd0)[((u & 63) << 1) | (u >> 6)] = 0.0f;
    __syncthreads();

    const float* tb = g_table + dir * 512 + rA;
    int pos = dir ? (SS - 1) : 0;
    const int stp = dir ? -1 : 1;

    const float* zrow = tb + (size_t)toks[pos] * 1024;
    float zl = zrow[0];
    float zh = zrow[256];

    for (int s = 0; s < SS; ++s) {
        float nzl = 0.0f, nzh = 0.0f;
        if (s + 1 < SS) {
            const float* np = tb + (size_t)toks[pos + stp] * 1024;
            nzl = np[0]; nzh = np[256];
        }

        const ulonglong2* hp =
            (s & 1) ? (const ulonglong2*)hd1 : (const ulonglong2*)hd0;

        ull accA0 = 0ull, accA1 = 0ull, accB0 = 0ull, accB1 = 0ull;
        #pragma unroll
        for (int q = 0; q < 16; ++q) {              // k = 0..31 | 64..95
            ulonglong2 h2 = hp[q];
            fma2(accA0, h2.x, wregA[2 * q]);
            fma2(accB0, h2.x, wregB[2 * q]);
            fma2(accA0, h2.y, wregA[2 * q + 1]);
            fma2(accB0, h2.y, wregB[2 * q + 1]);
        }
        #pragma unroll
        for (int q = 16; q < 28; ++q) {             // k = 32..55 | 96..119
            ulonglong2 h2 = hp[q];
            fma2(accA1, h2.x, wregA[2 * q]);
            fma2(accB1, h2.x, wregB[2 * q]);
            fma2(accA1, h2.y, wregA[2 * q + 1]);
            fma2(accB1, h2.y, wregB[2 * q + 1]);
        }
        #pragma unroll
        for (int q = 28; q < 32; ++q) {             // k = 56..63 | 120..127
            ulonglong2 h2 = hp[q];
            ulonglong2 wa = wsP2[((q - 28) * 2 + 0) * 256 + t];
            ulonglong2 wb = wsP2[((q - 28) * 2 + 1) * 256 + t];
            fma2(accA1, h2.x, wa.x);
            fma2(accB1, h2.x, wb.x);
            fma2(accA1, h2.y, wa.y);
            fma2(accB1, h2.y, wb.y);
        }

        float a0l, a0h, a1l, a1h, b0l, b0h, b1l, b1h;
        unpack2(accA0, a0l, a0h);   // a0l = S(0..31),  a0h = S(64..95)
        unpack2(accA1, a1l, a1h);   // a1l = S(32..63), a1h = S(96..127)
        unpack2(accB0, b0l, b0h);
        unpack2(accB1, b1l, b1h);
        float hwA = __fadd_rn(__fadd_rn(a0l, a1l), __fadd_rn(a0h, a1h));
        float hwB = __fadd_rn(__fadd_rn(b0l, b1l), __fadd_rn(b0h, b1h));

        float zA = __fadd_rn(__fadd_rn(zl, hwA), bA);   // par0: zi, par1: zf
        float zB = __fadd_rn(__fadd_rn(zh, hwB), bB);   // par0: zg, par1: zo

        // parallel nonlinearity tail (r15): both parities work
        float vA = sigmoid_xla(zA);
        float targ = par ? __fmul_rn(0.5f, zB) : zB;
        float tv   = tanh_xla(targ);
        float vB   = par ? __fadd_rn(__fmul_rn(0.5f, tv), 0.5f) : tv;

        ull opk = __shfl_xor_sync(0xffffffffu, pack2(vA, vB), 1);

        if (par == 0) {
            float iv = vA, gv = vB;
            float fv, ov; unpack2(opk, fv, ov);
            cst = __fadd_rn(__fmul_rn(fv, cst), __fmul_rn(iv, gv));
            float hv = __fmul_rn(ov, tanh_xla(cst));
            float* hdW = (float*)((s & 1) ? hd0 : hd1);   // write OTHER buffer
            hdW[((u & 63) << 1) | (u >> 6)] = hv;         // {h[k],h[k+64]} slot
            g_h[(size_t)(pos * BB + b) * 256 + dir * 128 + u] = hv;
        }
        __syncthreads();

        zl = nzl; zh = nzh;
        pos += stp;
    }
}

// =====================================================================
// K3: emissions. One warp per (s,b).
// =====================================================================
__global__ void __launch_bounds__(256) k3_emis(
    const float* __restrict__ w_out, const float* __restrict__ b_out)
{
    __shared__ float wsm[4 * 256];
    int tid = threadIdx.x;
    #pragma unroll
    for (int it = 0; it < 4; ++it) wsm[tid + 256 * it] = w_out[tid + 256 * it];
    __syncthreads();

    int w = tid >> 5, lane = tid & 31;
    int gid = blockIdx.x * 8 + w;
    int b = gid & 63, s = gid >> 6;
    const float* hrow = g_h + (size_t)(s * BB + b) * 256;

    float a0 = 0.f, a1 = 0.f, a2 = 0.f, a3 = 0.f;
    #pragma unroll
    for (int it = 0; it < 8; ++it) {
        int jj = it * 32 + lane;
        float hv = hrow[jj];
        a0 = __fmaf_rn(hv, wsm[jj],       a0);
        a1 = __fmaf_rn(hv, wsm[256 + jj], a1);
        a2 = __fmaf_rn(hv, wsm[512 + jj], a2);
        a3 = __fmaf_rn(hv, wsm[768 + jj], a3);
    }
    #pragma unroll
    for (int off = 16; off; off >>= 1) {
        a0 = __fadd_rn(a0, __shfl_xor_sync(0xffffffffu, a0, off));
        a1 = __fadd_rn(a1, __shfl_xor_sync(0xffffffffu, a1, off));
        a2 = __fadd_rn(a2, __shfl_xor_sync(0xffffffffu, a2, off));
        a3 = __fadd_rn(a3, __shfl_xor_sync(0xffffffffu, a3, off));
    }
    if (lane == 0) {
        float* dst = g_feats + (size_t)(b * SS + s) * 4;
        dst[0] = __fadd_rn(a0, b_out[0]);
        dst[1] = __fadd_rn(a1, b_out[1]);
        dst[2] = __fadd_rn(a2, b_out[2]);
        dst[3] = __fadd_rn(a3, b_out[3]);
    }
}

// =====================================================================
// K4: Viterbi (float output) — unchanged; clock canary.
// =====================================================================
__global__ void __launch_bounds__(128) k4_viterbi(
    const float* __restrict__ start_t, const float* __restrict__ end_t,
    const float* __restrict__ trans, float* __restrict__ out)
{
    __shared__ float fs[SS * 4];
    __shared__ unsigned char bp[SS * 4];
    __shared__ int path[SS];
    int tid = threadIdx.x;
    int b = blockIdx.x;

    const float* src = g_feats + (size_t)b * SS * 4;
    for (int i = tid; i < SS * 4; i += 128) fs[i] = src[i];
    __syncthreads();

    if (tid < 4) {
        const int t = tid;
        float tr0 = trans[0 * 4 + t], tr1 = trans[1 * 4 + t];
        float tr2 = trans[2 * 4 + t], tr3 = trans[3 * 4 + t];
        float score = __fadd_rn(start_t[t], fs[t]);
        for (int s = 1; s < SS; ++s) {
            float s0 = __shfl_sync(0xFu, score, 0);
            float s1 = __shfl_sync(0xFu, score, 1);
            float s2 = __shfl_sync(0xFu, score, 2);
            float s3 = __shfl_sync(0xFu, score, 3);
            float e  = fs[s * 4 + t];
            float v0 = __fadd_rn(__fadd_rn(s0, tr0), e);
            float v1 = __fadd_rn(__fadd_rn(s1, tr1), e);
            float v2 = __fadd_rn(__fadd_rn(s2, tr2), e);
            float v3 = __fadd_rn(__fadd_rn(s3, tr3), e);
            float best = v0; int bpi = 0;
            if (v1 > best) { best = v1; bpi = 1; }
            if (v2 > best) { best = v2; bpi = 2; }
            if (v3 > best) { best = v3; bpi = 3; }
            score = best;
            bp[s * 4 + t] = (unsigned char)bpi;
        }
        score = __fadd_rn(score, end_t[t]);
        float f0 = __shfl_sync(0xFu, score, 0);
        float f1 = __shfl_sync(0xFu, score, 1);
        float f2 = __shfl_sync(0xFu, score, 2);
        float f3 = __shfl_sync(0xFu, score, 3);
        __syncwarp(0xFu);
        if (t == 0) {
            float best = f0; int last = 0;
            if (f1 > best) { best = f1; last = 1; }
            if (f2 > best) { best = f2; last = 2; }
            if (f3 > best) { best = f3; last = 3; }
            int tag = last;
            path[SS - 1] = tag;
            for (int s = SS - 1; s >= 1; --s) {
                tag = bp[s * 4 + tag];
                path[s - 1] = tag;
            }
        }
    }
    __syncthreads();
    for (int i = tid; i < SS; i += 128)
        out[b * SS + i] = (float)path[i];
}

// =====================================================================
extern "C" void kernel_launch(void* const* d_in, const int* in_sizes, int n_in,
                              void* d_out, int out_size)
{
    const int*   sentences = (const int*)d_in[0];
    const float* embed   = (const float*)d_in[1];
    const float* w_ih_f  = (const float*)d_in[2];
    const float* w_hh_f  = (const float*)d_in[3];
    const float* b_ih_f  = (const float*)d_in[4];
    const float* b_hh_f  = (const float*)d_in[5];
    const float* w_ih_r  = (const float*)d_in[6];
    const float* w_hh_r  = (const float*)d_in[7];
    const float* b_ih_r  = (const float*)d_in[8];
    const float* b_hh_r  = (const float*)d_in[9];
    const float* w_out   = (const float*)d_in[10];
    const float* b_out   = (const float*)d_in[11];
    const float* start_t = (const float*)d_in[12];
    const float* end_t   = (const float*)d_in[13];
    const float* trans   = (const float*)d_in[14];

    // launch-shifters keep ncu's capture window on k2_lstm
    kdummy<<<1, 32>>>();
    kdummy<<<1, 32>>>();

    cudaFuncSetAttribute(k1_table, cudaFuncAttributeMaxDynamicSharedMemorySize, K1_SMEM);
    dim3 g1(8, 250);
    k1_table<<<g1, 256, K1_SMEM>>>(embed, w_ih_f, w_ih_r);

    cudaFuncSetAttribute(k2_lstm, cudaFuncAttributeMaxDynamicSharedMemorySize, K2_SMEM);
    k2_lstm<<<128, 256, K2_SMEM>>>(sentences, w_hh_f, w_hh_r,
                                   b_ih_f, b_hh_f, b_ih_r, b_hh_r);

    k3_emis<<<8192, 256>>>(w_out, b_out);
    k4_viterbi<<<64, 128>>>(start_t, end_t, trans, (float*)d_out);
}